// round 7
// baseline (speedup 1.0000x reference)
#include <cuda_runtime.h>

#define D1C   16
#define D2C   16
#define NCC   64
#define NCPCC 8
// Inner o-block: 128 data floats + 8 norms + 4 pad = 140 floats (16B-aligned rows).
#define ISTRIDE 140
#define P 4

typedef unsigned long long u64;

__device__ __forceinline__ u64 ffma2(u64 a, u64 b, u64 c) {
    u64 d; asm("fma.rn.f32x2 %0, %1, %2, %3;" : "=l"(d) : "l"(a), "l"(b), "l"(c)); return d;
}
__device__ __forceinline__ u64 fmul2(u64 a, u64 b) {
    u64 d; asm("mul.rn.f32x2 %0, %1, %2;" : "=l"(d) : "l"(a), "l"(b)); return d;
}
__device__ __forceinline__ float hsum2(u64 v) {
    float lo, hi;
    asm("mov.b64 {%0, %1}, %2;" : "=f"(lo), "=f"(hi) : "l"(v));
    return lo + hi;
}
__device__ __forceinline__ u64 packf2(float lo, float hi) {
    u64 r; asm("mov.b64 %0, {%1, %2};" : "=l"(r) : "f"(lo), "f"(hi)); return r;
}

__global__ void __launch_bounds__(256, 2)
cluster_kernel(const float* __restrict__ x,
               const float* __restrict__ co,
               const float* __restrict__ ci,
               float* __restrict__ out, int n)
{
    __shared__ __align__(16) float s_oc[NCC * D1C];     // outer centers [c][d]
    __shared__ __align__(16) float s_on[NCC];           // outer ||c||^2
    __shared__ __align__(16) float s_in[NCC * ISTRIDE]; // inner [o]{128 data | 8 norms | pad}

    const int tid = threadIdx.x;

    for (int idx = tid; idx < NCC * D1C; idx += 256)
        s_oc[idx] = co[idx];
    for (int idx = tid; idx < NCC * NCPCC * D2C; idx += 256) {
        int o = idx >> 7, r = idx & 127;            // ci is [o][k][d]
        s_in[o * ISTRIDE + r] = ci[idx];
    }
    __syncthreads();

    for (int c = tid; c < NCC; c += 256) {
        float s = 0.f;
        #pragma unroll
        for (int d = 0; d < D1C; d++) { float v = s_oc[c * D1C + d]; s += v * v; }
        s_on[c] = s;
    }
    for (int idx = tid; idx < NCC * NCPCC; idx += 256) {
        int o = idx >> 3, k = idx & 7;
        float s = 0.f;
        #pragma unroll
        for (int d = 0; d < D2C; d++) { float v = s_in[o * ISTRIDE + k * D2C + d]; s += v * v; }
        s_in[o * ISTRIDE + 128 + k] = s;            // norms in pad region
    }
    __syncthreads();

    const int GS   = gridDim.x * blockDim.x;
    const u64 neg2 = packf2(-2.f, -2.f);

    for (int base = blockIdx.x * blockDim.x + tid; base < n; base += P * GS) {
        int idxp[P];
        #pragma unroll
        for (int p = 0; p < P; p++) {
            int t = base + p * GS;
            idxp[p] = (t < n) ? t : base;           // clamp: in-range dup, store guarded
        }

        // ---- load x1 (dims 0-15) for 4 points, pre-scaled by -2, packed f32x2 ----
        u64 px[P][8];
        #pragma unroll
        for (int p = 0; p < P; p++) {
            const ulonglong2* xp = (const ulonglong2*)(x + (size_t)idxp[p] * 32);
            ulonglong2 w0 = xp[0], w1 = xp[1], w2 = xp[2], w3 = xp[3];
            px[p][0] = fmul2(w0.x, neg2); px[p][1] = fmul2(w0.y, neg2);
            px[p][2] = fmul2(w1.x, neg2); px[p][3] = fmul2(w1.y, neg2);
            px[p][4] = fmul2(w2.x, neg2); px[p][5] = fmul2(w2.y, neg2);
            px[p][6] = fmul2(w3.x, neg2); px[p][7] = fmul2(w3.y, neg2);
        }

        // ---- outer argmin: d = ||c||^2 + sum((-2x).c), strict <, first wins ----
        float best[P]; int bo[P];
        #pragma unroll
        for (int p = 0; p < P; p++) { best[p] = 3.402823466e38f; bo[p] = 0; }

        #pragma unroll 1
        for (int cg = 0; cg < NCC / 4; cg++) {
            float4 nr = *(const float4*)(s_on + cg * 4);
            float nrr[4] = {nr.x, nr.y, nr.z, nr.w};
            #pragma unroll
            for (int j = 0; j < 4; j++) {
                int c = cg * 4 + j;
                const ulonglong2* cp = (const ulonglong2*)(s_oc + c * D1C);
                ulonglong2 m0 = cp[0], m1 = cp[1], m2 = cp[2], m3 = cp[3];
                u64 ninit = packf2(nrr[j], 0.f);    // acc starts at (norm, 0)

                u64 acc[P];
                #pragma unroll
                for (int p = 0; p < P; p++) acc[p] = ffma2(px[p][0], m0.x, ninit);
                #pragma unroll
                for (int p = 0; p < P; p++) acc[p] = ffma2(px[p][1], m0.y, acc[p]);
                #pragma unroll
                for (int p = 0; p < P; p++) acc[p] = ffma2(px[p][2], m1.x, acc[p]);
                #pragma unroll
                for (int p = 0; p < P; p++) acc[p] = ffma2(px[p][3], m1.y, acc[p]);
                #pragma unroll
                for (int p = 0; p < P; p++) acc[p] = ffma2(px[p][4], m2.x, acc[p]);
                #pragma unroll
                for (int p = 0; p < P; p++) acc[p] = ffma2(px[p][5], m2.y, acc[p]);
                #pragma unroll
                for (int p = 0; p < P; p++) acc[p] = ffma2(px[p][6], m3.x, acc[p]);
                #pragma unroll
                for (int p = 0; p < P; p++) acc[p] = ffma2(px[p][7], m3.y, acc[p]);

                #pragma unroll
                for (int p = 0; p < P; p++) {
                    float dd = hsum2(acc[p]);
                    if (dd < best[p]) { best[p] = dd; bo[p] = c; }
                }
            }
        }

        // ---- inner argmin; x2 reloaded (L2-hot), processed in pairs ----
        float res[P];
        #pragma unroll
        for (int pp = 0; pp < P; pp += 2) {
            const ulonglong2* q0 = (const ulonglong2*)(x + (size_t)idxp[pp] * 32);
            const ulonglong2* q1 = (const ulonglong2*)(x + (size_t)idxp[pp + 1] * 32);
            ulonglong2 v00 = q0[4], v01 = q0[5], v02 = q0[6], v03 = q0[7];
            ulonglong2 v10 = q1[4], v11 = q1[5], v12 = q1[6], v13 = q1[7];

            u64 py0[8] = {fmul2(v00.x, neg2), fmul2(v00.y, neg2),
                          fmul2(v01.x, neg2), fmul2(v01.y, neg2),
                          fmul2(v02.x, neg2), fmul2(v02.y, neg2),
                          fmul2(v03.x, neg2), fmul2(v03.y, neg2)};
            u64 py1[8] = {fmul2(v10.x, neg2), fmul2(v10.y, neg2),
                          fmul2(v11.x, neg2), fmul2(v11.y, neg2),
                          fmul2(v12.x, neg2), fmul2(v12.y, neg2),
                          fmul2(v13.x, neg2), fmul2(v13.y, neg2)};

            const float* ib0 = s_in + bo[pp]     * ISTRIDE;
            const float* ib1 = s_in + bo[pp + 1] * ISTRIDE;

            float4 nA0 = *(const float4*)(ib0 + 128), nB0 = *(const float4*)(ib0 + 132);
            float4 nA1 = *(const float4*)(ib1 + 128), nB1 = *(const float4*)(ib1 + 132);
            float nk0[8] = {nA0.x, nA0.y, nA0.z, nA0.w, nB0.x, nB0.y, nB0.z, nB0.w};
            float nk1[8] = {nA1.x, nA1.y, nA1.z, nA1.w, nB1.x, nB1.y, nB1.z, nB1.w};

            float b0v = 3.402823466e38f, b1v = 3.402823466e38f;
            int   bk0 = 0, bk1 = 0;

            #pragma unroll
            for (int k = 0; k < NCPCC; k++) {
                const ulonglong2* kp0 = (const ulonglong2*)(ib0 + k * D2C);
                const ulonglong2* kp1 = (const ulonglong2*)(ib1 + k * D2C);
                ulonglong2 ma = kp0[0], mb = kp0[1], mc = kp0[2], md = kp0[3];
                ulonglong2 me = kp1[0], mf = kp1[1], mg = kp1[2], mh = kp1[3];

                u64 s0 = ffma2(py0[0], ma.x, packf2(nk0[k], 0.f));
                u64 s1 = ffma2(py1[0], me.x, packf2(nk1[k], 0.f));
                s0 = ffma2(py0[1], ma.y, s0);  s1 = ffma2(py1[1], me.y, s1);
                s0 = ffma2(py0[2], mb.x, s0);  s1 = ffma2(py1[2], mf.x, s1);
                s0 = ffma2(py0[3], mb.y, s0);  s1 = ffma2(py1[3], mf.y, s1);
                s0 = ffma2(py0[4], mc.x, s0);  s1 = ffma2(py1[4], mg.x, s1);
                s0 = ffma2(py0[5], mc.y, s0);  s1 = ffma2(py1[5], mg.y, s1);
                s0 = ffma2(py0[6], md.x, s0);  s1 = ffma2(py1[6], mh.x, s1);
                s0 = ffma2(py0[7], md.y, s0);  s1 = ffma2(py1[7], mh.y, s1);

                float dd0 = hsum2(s0), dd1 = hsum2(s1);
                if (dd0 < b0v) { b0v = dd0; bk0 = k; }
                if (dd1 < b1v) { b1v = dd1; bk1 = k; }
            }
            res[pp]     = (float)(bo[pp]     * NCPCC + bk0);
            res[pp + 1] = (float)(bo[pp + 1] * NCPCC + bk1);
        }

        #pragma unroll
        for (int p = 0; p < P; p++) {
            int t = base + p * GS;
            if (t < n) out[t] = res[p];
        }
    }
}

extern "C" void kernel_launch(void* const* d_in, const int* in_sizes, int n_in,
                              void* d_out, int out_size)
{
    // Bind inputs by unique element counts (robust to metadata ordering).
    const float* x  = 0; const float* co = 0; const float* ci = 0;
    long long x_elems = 0;
    for (int i = 0; i < n_in; i++) {
        int sz = in_sizes[i];
        if (sz == NCC * D1C)              co = (const float*)d_in[i];
        else if (sz == NCC * NCPCC * D2C) ci = (const float*)d_in[i];
        else { x = (const float*)d_in[i]; x_elems = sz; }
    }
    if (!x)  { x  = (const float*)d_in[0]; x_elems = in_sizes[0]; }
    if (!co)   co = (const float*)d_in[1];
    if (!ci)   ci = (const float*)d_in[2];

    float* out = (float*)d_out;
    int n = (int)(x_elems / (D1C + D2C));
    if (n <= 0 || n > out_size) n = out_size;

    int blocks = 296;  // 148 SMs x 2 CTAs, grid-stride, P=4 points/thread
    cluster_kernel<<<blocks, 256>>>(x, co, ci, out, n);
}

// round 9
// speedup vs baseline: 1.1485x; 1.1485x over previous
#include <cuda_runtime.h>

#define D1C   16
#define D2C   16
#define NCC   64
#define NCPCC 8
// Inner o-block: 128 data floats + 8 norms + 4 pad = 140 floats.
// Quad stride 35 == 3 (mod 8) -> distinct bo spread across all 8 quad-banks.
#define ISTRIDE 140
#define P 4

typedef unsigned long long u64;

__device__ __forceinline__ u64 ffma2(u64 a, u64 b, u64 c) {
    u64 d; asm("fma.rn.f32x2 %0, %1, %2, %3;" : "=l"(d) : "l"(a), "l"(b), "l"(c)); return d;
}
__device__ __forceinline__ u64 fmul2(u64 a, u64 b) {
    u64 d; asm("mul.rn.f32x2 %0, %1, %2;" : "=l"(d) : "l"(a), "l"(b)); return d;
}
__device__ __forceinline__ float hsum2(u64 v) {
    float lo, hi;
    asm("mov.b64 {%0, %1}, %2;" : "=f"(lo), "=f"(hi) : "l"(v));
    return lo + hi;
}
__device__ __forceinline__ u64 packf2(float lo, float hi) {
    u64 r; asm("mov.b64 %0, {%1, %2};" : "=l"(r) : "f"(lo), "f"(hi)); return r;
}

__global__ void __launch_bounds__(256, 2)
cluster_kernel(const float* __restrict__ x,
               const float* __restrict__ co,
               const float* __restrict__ ci,
               float* __restrict__ out, int n)
{
    __shared__ __align__(16) float s_oc[NCC * D1C];     // outer centers [c][d]
    __shared__ __align__(16) float s_on[NCC];           // outer ||c||^2
    __shared__ __align__(16) float s_in[NCC * ISTRIDE]; // inner [o]{128 data | 8 norms | pad}

    const int tid = threadIdx.x;

    for (int idx = tid; idx < NCC * D1C; idx += 256)
        s_oc[idx] = co[idx];
    for (int idx = tid; idx < NCC * NCPCC * D2C; idx += 256) {
        int o = idx >> 7, r = idx & 127;            // ci is [o][k][d]
        s_in[o * ISTRIDE + r] = ci[idx];
    }
    __syncthreads();

    for (int c = tid; c < NCC; c += 256) {
        float s = 0.f;
        #pragma unroll
        for (int d = 0; d < D1C; d++) { float v = s_oc[c * D1C + d]; s += v * v; }
        s_on[c] = s;
    }
    for (int idx = tid; idx < NCC * NCPCC; idx += 256) {
        int o = idx >> 3, k = idx & 7;
        float s = 0.f;
        #pragma unroll
        for (int d = 0; d < D2C; d++) { float v = s_in[o * ISTRIDE + k * D2C + d]; s += v * v; }
        s_in[o * ISTRIDE + 128 + k] = s;            // norms in pad region
    }
    __syncthreads();

    const int GS   = gridDim.x * blockDim.x;
    const u64 neg2 = packf2(-2.f, -2.f);

    // Thread handles P=4 CONTIGUOUS points [p0, p0+4): zero tail waste when
    // 4|n, float4 output store, x row group = one contiguous 512B region.
    for (int p0 = (blockIdx.x * blockDim.x + tid) * P; p0 < n; p0 += P * GS) {
        const ulonglong2* xb = (const ulonglong2*)(x + (size_t)p0 * 32);
        const bool full = (p0 + P <= n);

        // per-point ulonglong2 offset into xb (clamped to point 0 if ragged)
        int off[P];
        #pragma unroll
        for (int p = 0; p < P; p++)
            off[p] = (full || p0 + p < n) ? p * 8 : 0;

        // ---- x1 (dims 0-15) of 4 points, pre-scaled by -2, packed f32x2 ----
        u64 px[P][8];
        #pragma unroll
        for (int p = 0; p < P; p++) {
            ulonglong2 w0 = xb[off[p] + 0], w1 = xb[off[p] + 1];
            ulonglong2 w2 = xb[off[p] + 2], w3 = xb[off[p] + 3];
            px[p][0] = fmul2(w0.x, neg2); px[p][1] = fmul2(w0.y, neg2);
            px[p][2] = fmul2(w1.x, neg2); px[p][3] = fmul2(w1.y, neg2);
            px[p][4] = fmul2(w2.x, neg2); px[p][5] = fmul2(w2.y, neg2);
            px[p][6] = fmul2(w3.x, neg2); px[p][7] = fmul2(w3.y, neg2);
        }

        // ---- outer argmin: d = ||c||^2 + sum((-2x).c), strict <, first wins ----
        float best[P]; int bo[P];
        #pragma unroll
        for (int p = 0; p < P; p++) { best[p] = 3.402823466e38f; bo[p] = 0; }

        #pragma unroll 1
        for (int cg = 0; cg < NCC / 4; cg++) {
            float4 nr = *(const float4*)(s_on + cg * 4);
            float nrr[4] = {nr.x, nr.y, nr.z, nr.w};
            #pragma unroll
            for (int j = 0; j < 4; j++) {
                int c = cg * 4 + j;
                const ulonglong2* cp = (const ulonglong2*)(s_oc + c * D1C);
                ulonglong2 m0 = cp[0], m1 = cp[1], m2 = cp[2], m3 = cp[3];
                u64 ninit = packf2(nrr[j], 0.f);

                u64 acc[P];
                #pragma unroll
                for (int p = 0; p < P; p++) acc[p] = ffma2(px[p][0], m0.x, ninit);
                #pragma unroll
                for (int p = 0; p < P; p++) acc[p] = ffma2(px[p][1], m0.y, acc[p]);
                #pragma unroll
                for (int p = 0; p < P; p++) acc[p] = ffma2(px[p][2], m1.x, acc[p]);
                #pragma unroll
                for (int p = 0; p < P; p++) acc[p] = ffma2(px[p][3], m1.y, acc[p]);
                #pragma unroll
                for (int p = 0; p < P; p++) acc[p] = ffma2(px[p][4], m2.x, acc[p]);
                #pragma unroll
                for (int p = 0; p < P; p++) acc[p] = ffma2(px[p][5], m2.y, acc[p]);
                #pragma unroll
                for (int p = 0; p < P; p++) acc[p] = ffma2(px[p][6], m3.x, acc[p]);
                #pragma unroll
                for (int p = 0; p < P; p++) acc[p] = ffma2(px[p][7], m3.y, acc[p]);

                #pragma unroll
                for (int p = 0; p < P; p++) {
                    float dd = hsum2(acc[p]);
                    if (dd < best[p]) { best[p] = dd; bo[p] = c; }
                }
            }
        }

        // ---- inner argmin, per point (minimal live state -> no spills) ----
        float res[P];
        #pragma unroll
        for (int p = 0; p < P; p++) {
            ulonglong2 v0 = xb[off[p] + 4], v1 = xb[off[p] + 5];
            ulonglong2 v2 = xb[off[p] + 6], v3 = xb[off[p] + 7];
            u64 py[8] = {fmul2(v0.x, neg2), fmul2(v0.y, neg2),
                         fmul2(v1.x, neg2), fmul2(v1.y, neg2),
                         fmul2(v2.x, neg2), fmul2(v2.y, neg2),
                         fmul2(v3.x, neg2), fmul2(v3.y, neg2)};

            const float* ib = s_in + bo[p] * ISTRIDE;
            float4 nA = *(const float4*)(ib + 128);
            float4 nB = *(const float4*)(ib + 132);
            float nk[8] = {nA.x, nA.y, nA.z, nA.w, nB.x, nB.y, nB.z, nB.w};

            float bd = 3.402823466e38f; int bk = 0;
            #pragma unroll
            for (int k = 0; k < NCPCC; k++) {
                const ulonglong2* kp = (const ulonglong2*)(ib + k * D2C);
                ulonglong2 ma = kp[0], mb = kp[1], mc = kp[2], md = kp[3];

                u64 s = ffma2(py[0], ma.x, packf2(nk[k], 0.f));
                s = ffma2(py[1], ma.y, s);
                s = ffma2(py[2], mb.x, s);
                s = ffma2(py[3], mb.y, s);
                s = ffma2(py[4], mc.x, s);
                s = ffma2(py[5], mc.y, s);
                s = ffma2(py[6], md.x, s);
                s = ffma2(py[7], md.y, s);

                float dd = hsum2(s);
                if (dd < bd) { bd = dd; bk = k; }
            }
            res[p] = (float)(bo[p] * NCPCC + bk);
        }

        if (full) {
            *(float4*)(out + p0) = make_float4(res[0], res[1], res[2], res[3]);
        } else {
            #pragma unroll
            for (int p = 0; p < P; p++)
                if (p0 + p < n) out[p0 + p] = res[p];
        }
    }
}

extern "C" void kernel_launch(void* const* d_in, const int* in_sizes, int n_in,
                              void* d_out, int out_size)
{
    // Bind inputs by unique element counts (robust to metadata ordering).
    const float* x  = 0; const float* co = 0; const float* ci = 0;
    long long x_elems = 0;
    for (int i = 0; i < n_in; i++) {
        int sz = in_sizes[i];
        if (sz == NCC * D1C)              co = (const float*)d_in[i];
        else if (sz == NCC * NCPCC * D2C) ci = (const float*)d_in[i];
        else { x = (const float*)d_in[i]; x_elems = sz; }
    }
    if (!x)  { x  = (const float*)d_in[0]; x_elems = in_sizes[0]; }
    if (!co)   co = (const float*)d_in[1];
    if (!ci)   ci = (const float*)d_in[2];

    float* out = (float*)d_out;
    int n = (int)(x_elems / (D1C + D2C));
    if (n <= 0 || n > out_size) n = out_size;

    int blocks = 296;  // 148 SMs x 2 CTAs resident, grid-stride, P=4 contiguous
    cluster_kernel<<<blocks, 256>>>(x, co, ci, out, n);
}